// round 8
// baseline (speedup 1.0000x reference)
#include <cuda_runtime.h>
#include <cstdint>

#define B_SZ 16384
#define IN_DIM 784
#define HID 400
#define T_STEPS 20
#define NB 25             // n-blocks of 16 columns
#define KC 25             // k-chunks of 32 (K padded 784->800)
#define BNB 38400u        // bytes per n-block (all 3 digits)
#define B01SZ 25600u      // digits 0,1 region within a block
#define OFF_B   0u        // 2 x 38400
#define OFF_AM  76800u    // 12800 (single mask buffer)
#define OFF_F   89600u    // 400 x 12 floats
#define OFF_H2M 108800u   // 128 x 10 floats
#define OFF_H2S 113920u   // 128 x 10 floats
#define OFF_H2P 119040u   // 128 x 10 floats (cross-warp partial)
#define OFF_B2  124160u   // 10 floats
#define SMEM_REQ 124224

__device__ __align__(128) uint8_t g_wq[NB * BNB];  // quantized W1 digits
__device__ float g_c1[HID * B_SZ];                 // LIF1 carry, transposed [n][m]

struct KeyArr { unsigned a[T_STEPS], b[T_STEPS]; };

// ---------------- threefry2x32 (exact JAX semantics) ----------------
__host__ __device__ __forceinline__ void tfr(unsigned &x0, unsigned &x1, int r){
  x0 += x1;
#ifdef __CUDA_ARCH__
  x1 = __funnelshift_l(x1, x1, r);
#else
  x1 = (x1 << r) | (x1 >> (32 - r));
#endif
  x1 ^= x0;
}
__host__ __device__ __forceinline__ void tf2x32(unsigned k0, unsigned k1,
                                                unsigned x0, unsigned x1,
                                                unsigned &o0, unsigned &o1){
  unsigned k2 = k0 ^ k1 ^ 0x1BD11BDAu;
  x0 += k0; x1 += k1;
  tfr(x0,x1,13); tfr(x0,x1,15); tfr(x0,x1,26); tfr(x0,x1,6);  x0 += k1; x1 += k2 + 1u;
  tfr(x0,x1,17); tfr(x0,x1,29); tfr(x0,x1,16); tfr(x0,x1,24); x0 += k2; x1 += k0 + 2u;
  tfr(x0,x1,13); tfr(x0,x1,15); tfr(x0,x1,26); tfr(x0,x1,6);  x0 += k0; x1 += k1 + 3u;
  tfr(x0,x1,17); tfr(x0,x1,29); tfr(x0,x1,16); tfr(x0,x1,24); x0 += k1; x1 += k2 + 4u;
  tfr(x0,x1,13); tfr(x0,x1,15); tfr(x0,x1,26); tfr(x0,x1,6);  x0 += k2; x1 += k0 + 5u;
  o0 = x0; o1 = x1;
}
__device__ __forceinline__ float tf_u01(unsigned ka, unsigned kb, unsigned i){
  unsigned o0, o1; tf2x32(ka, kb, 0u, i, o0, o1);
  return __uint_as_float((((o0 ^ o1) >> 9) | 0x3f800000u)) - 1.0f;
}

// ---------------- prep: fp32 W1 -> 3 int8 digits (scale 2^24) ----------------
__global__ __launch_bounds__(256) void prep(const float* __restrict__ W1){
  int i = blockIdx.x * 256 + threadIdx.x;
  if (i >= HID * 800) return;
  int n = i / 800, k = i % 800;
  float w = (k < IN_DIM) ? W1[n * IN_DIM + k] : 0.0f;
  int v = __float2int_rn(w * 16777216.0f);          // w * 2^24
  int d0 = ((v & 0xFF) ^ 0x80) - 0x80;  v = (v - d0) >> 8;
  int d1 = ((v & 0xFF) ^ 0x80) - 0x80;  v = (v - d1) >> 8;
  int d2 = v;
  int nb = n / 16, nn = n % 16;
  int kc = k >> 5, kk = k & 31;
  int half = kk >> 4, tig = (kk & 15) >> 2, j = kk & 3;
  unsigned grp = (unsigned)(nn * KC + kc) * 4u + (unsigned)tig;
  uint8_t* base = g_wq + (unsigned)nb * BNB;
  base[grp * 16u + 0u + half * 4u + j]   = (uint8_t)d0;
  base[grp * 16u + 8u + half * 4u + j]   = (uint8_t)d1;
  base[B01SZ + grp * 8u + half * 4u + j] = (uint8_t)d2;
}

// ---------------- device helpers ----------------
__device__ __forceinline__ uint32_t s2u(const void* p){
  uint32_t a; asm("{ .reg .u64 t; cvta.to.shared.u64 t, %1; cvt.u32.u64 %0, t; }" : "=r"(a) : "l"(p));
  return a;
}
__device__ __forceinline__ void imma(int* c, uint32_t a0, uint32_t a1, uint32_t a2,
                                     uint32_t a3, uint32_t b0, uint32_t b1){
  asm volatile("mma.sync.aligned.m16n8k32.row.col.s32.s8.s8.s32 "
               "{%0,%1,%2,%3}, {%4,%5,%6,%7}, {%8,%9}, {%0,%1,%2,%3};"
               : "+r"(c[0]), "+r"(c[1]), "+r"(c[2]), "+r"(c[3])
               : "r"(a0), "r"(a1), "r"(a2), "r"(a3), "r"(b0), "r"(b1));
}
__device__ __forceinline__ void cp_fill(uint8_t* dst, const uint8_t* src, int tid){
  uint32_t d = s2u(dst);
  for (unsigned ofs = (unsigned)tid * 16u; ofs < BNB; ofs += 8192u)
    asm volatile("cp.async.cg.shared.global [%0], [%1], 16;" :: "r"(d + ofs), "l"(src + ofs));
}
__device__ __forceinline__ uint32_t gen_word(const float* __restrict__ x,
                                             unsigned ka, unsigned kb, int cta, int w){
  int row = w / 25, wi = w - row * 25;
  unsigned i0 = (unsigned)(cta * 128 + row) * IN_DIM + (unsigned)(wi * 32);
  const float4* xp = (const float4*)(x + i0);
  int QQ = (wi == 24) ? 4 : 8;
  uint32_t word = 0u;
  #pragma unroll 4
  for (int q = 0; q < QQ; q++){
    float4 xv = __ldg(xp + q);
    unsigned ib = i0 + (unsigned)(q * 4);
    word |= (xv.x > tf_u01(ka, kb, ib + 0u)) ? (1u << (q * 4 + 0)) : 0u;
    word |= (xv.y > tf_u01(ka, kb, ib + 1u)) ? (1u << (q * 4 + 1)) : 0u;
    word |= (xv.z > tf_u01(ka, kb, ib + 2u)) ? (1u << (q * 4 + 2)) : 0u;
    word |= (xv.w > tf_u01(ka, kb, ib + 3u)) ? (1u << (q * 4 + 3)) : 0u;
  }
  return word;
}

// ---------------- persistent SNN kernel: 16 mma warps ----------------
__global__ __launch_bounds__(512, 1) void snn(const float* __restrict__ x,
                                              const float* __restrict__ W2,
                                              const float* __restrict__ b1,
                                              const float* __restrict__ b2,
                                              float* __restrict__ out, KeyArr keys){
  extern __shared__ uint8_t SM[];
  float* Ftab = (float*)(SM + OFF_F);
  float* Sh2m = (float*)(SM + OFF_H2M);
  float* Sh2s = (float*)(SM + OFF_H2S);
  float* Sh2p = (float*)(SM + OFF_H2P);
  float* Sb2  = (float*)(SM + OFF_B2);
  uint32_t* AM = (uint32_t*)(SM + OFF_AM);
  int tid = threadIdx.x, lane = tid & 31, wid = tid >> 5, cta = blockIdx.x;
  int g = lane >> 2, tig = lane & 3;
  int u = wid >> 1, h = wid & 1;          // row unit 0..7, n8-half 0..1

  // smem tables
  for (int i = tid; i < HID * 12; i += 512){
    int n = i / 12, o = i % 12;
    Ftab[i] = (o < 10) ? W2[o * HID + n] : (o == 10 ? b1[n] : 0.0f);
  }
  for (int i = tid; i < 1280; i += 512){ Sh2m[i] = 0.0f; Sh2s[i] = 0.0f; }
  if (tid < 10) Sb2[tid] = b2[tid];

  // prefetch first weight block
  cp_fill(SM + OFF_B, g_wq, tid);
  asm volatile("cp.async.commit_group;" ::: "memory");

  int rA = u * 16 + g, rB = rA + 8;       // local rows
  int mA = cta * 128 + rA, mB = mA + 8;
  int gbase = g * 100 + tig;

  for (int t = 0; t < T_STEPS; t++){
    // ---- serial mask generation (all 512 threads, ~1% of t) ----
    __syncthreads();                       // prev t fully consumed AM
    unsigned ka = keys.a[t], kb = keys.b[t];
    #pragma unroll
    for (int j = 0; j < 7; j++){
      int w = tid + (j << 9);
      if (w < 3200) AM[w] = gen_word(x, ka, kb, cta, w);
    }
    __syncthreads();                       // masks visible

    float acc10[2][10] = {};
    for (int nb = 0; nb < NB; nb++){
      int seq = t * NB + nb;
      __syncthreads();                     // buffer (seq+1)&1 free
      if (seq + 1 < T_STEPS * NB){
        cp_fill(SM + OFF_B + (unsigned)((seq + 1) & 1) * BNB,
                g_wq + (unsigned)((nb + 1) % NB) * BNB, tid);
        asm volatile("cp.async.commit_group;" ::: "memory");
        asm volatile("cp.async.wait_group 1;" ::: "memory");
      } else {
        asm volatile("cp.async.wait_group 0;" ::: "memory");
      }
      __syncthreads();                     // buffer seq&1 loaded

      const uint8_t* Bb = SM + OFF_B + (unsigned)(seq & 1) * BNB;
      int accd[3][4] = {};

      #pragma unroll 5
      for (int kc = 0; kc < KC; kc++){
        uint32_t mAv = AM[rA * 25 + kc], mBv = AM[rB * 25 + kc];
        uint32_t sa = mAv >> (tig * 4), sb = mBv >> (tig * 4);
        uint32_t a0 = ((sa & 0xFu) * 0x204081u) & 0x01010101u;
        uint32_t a2 = (((sa >> 16) & 0xFu) * 0x204081u) & 0x01010101u;
        uint32_t a1 = ((sb & 0xFu) * 0x204081u) & 0x01010101u;
        uint32_t a3 = (((sb >> 16) & 0xFu) * 0x204081u) & 0x01010101u;
        unsigned grp = (unsigned)(h * 800 + kc * 4 + gbase);
        uint4 v01 = *(const uint4*)(Bb + grp * 16u);
        uint2 v2  = *(const uint2*)(Bb + B01SZ + grp * 8u);
        imma(accd[0], a0, a1, a2, a3, v01.x, v01.y);   // d0
        imma(accd[1], a0, a1, a2, a3, v01.z, v01.w);   // d1
        imma(accd[2], a0, a1, a2, a3, v2.x,  v2.y);    // d2
      }

      // epilogue: combine digits -> LIF1 -> GEMM2 partial (this warp's 8 cols)
      #pragma unroll
      for (int j = 0; j < 2; j++){
        int n = nb * 16 + h * 8 + 2 * tig + j;
        const float4* Fp = (const float4*)(Ftab + n * 12);
        float4 F0 = Fp[0], F1 = Fp[1], F2 = Fp[2];     // w0..w9, b1 = F2.z
        #pragma unroll
        for (int r = 0; r < 2; r++){
          int ri = r * 2 + j;
          float f = fmaf(__int2float_rn(accd[2][ri]), 0.00390625f,
                    fmaf(__int2float_rn(accd[1][ri]), 1.52587890625e-05f,
                         __int2float_rn(accd[0][ri]) * 5.9604644775390625e-08f));
          int m = r ? mB : mA;
          float* cp_ = g_c1 + (size_t)n * B_SZ + m;    // transposed, coalesced
          float carry = t ? *cp_ : 0.0f;
          float mem = (carry + f) + F2.z;
          bool s = mem > 0.5f;
          *cp_ = s ? 0.0f : 0.2f * mem;
          if (s){
            acc10[r][0] += F0.x; acc10[r][1] += F0.y; acc10[r][2] += F0.z; acc10[r][3] += F0.w;
            acc10[r][4] += F1.x; acc10[r][5] += F1.y; acc10[r][6] += F1.z; acc10[r][7] += F1.w;
            acc10[r][8] += F2.x; acc10[r][9] += F2.y;
          }
        }
      }
    }

    // ---- LIF2: reduce over tig lanes, then combine the two halves via smem ----
    #pragma unroll
    for (int r = 0; r < 2; r++){
      #pragma unroll
      for (int o = 0; o < 10; o++){
        float v = acc10[r][o];
        v += __shfl_xor_sync(0xffffffffu, v, 1);
        v += __shfl_xor_sync(0xffffffffu, v, 2);
        acc10[r][o] = v;
      }
    }
    if (h == 0 && tig == 0){
      #pragma unroll
      for (int r = 0; r < 2; r++){
        int rl = r ? rB : rA;
        #pragma unroll
        for (int o = 0; o < 10; o++) Sh2p[rl * 10 + o] = acc10[r][o];
      }
    }
    __syncthreads();
    if (h == 1 && tig == 0){
      #pragma unroll
      for (int r = 0; r < 2; r++){
        int rl = r ? rB : rA;
        #pragma unroll
        for (int o = 0; o < 10; o++){
          float v = Sh2p[rl * 10 + o] + acc10[r][o];
          float m2 = (Sh2m[rl * 10 + o] + v) + Sb2[o];
          bool s2 = m2 > 0.5f;
          Sh2m[rl * 10 + o] = s2 ? 0.0f : 0.2f * m2;
          Sh2s[rl * 10 + o] += s2 ? 1.0f : 0.0f;
        }
      }
    }
  }
  __syncthreads();

  // output
  for (int i = tid; i < 1280; i += 512){
    int m = i / 10, o = i % 10;
    out[(cta * 128 + m) * 10 + o] = Sh2s[m * 10 + o] * 0.05f;
  }
}

// ---------------- launch ----------------
extern "C" void kernel_launch(void* const* d_in, const int* in_sizes, int n_in,
                              void* d_out, int out_size){
  const float* x  = (const float*)d_in[0];
  const float* W1 = (const float*)d_in[1];
  const float* b1 = (const float*)d_in[2];
  const float* W2 = (const float*)d_in[3];
  const float* b2 = (const float*)d_in[4];
  float* out = (float*)d_out;

  KeyArr keys;
  for (int t = 0; t < T_STEPS; t++){
    unsigned o0, o1;
    tf2x32(0u, 42u, 0u, (unsigned)t, o0, o1);
    keys.a[t] = o0; keys.b[t] = o1;
  }

  cudaFuncSetAttribute(snn, cudaFuncAttributeMaxDynamicSharedMemorySize, SMEM_REQ);
  prep<<<(HID * 800 + 255) / 256, 256>>>(W1);
  snn<<<128, 512, SMEM_REQ>>>(x, W2, b1, b2, out, keys);
}

// round 9
// speedup vs baseline: 1.0521x; 1.0521x over previous
#include <cuda_runtime.h>
#include <cstdint>

#define B_SZ 16384
#define IN_DIM 784
#define HID 400
#define T_STEPS 20
#define MT 112            // rows per CTA
#define NCTA 148
#define CSTRIDE 16576u    // padded row stride for carry (148*112)
#define NB 25             // n-blocks of 16 columns
#define KC 25             // k-chunks of 32 (K padded 784->800)
#define BNB 38400u        // bytes per n-block (all 3 digits)
#define B01SZ 25600u      // digits 0,1 region within a block
#define NW 2800           // mask words per buffer (112*25)
#define OFF_B   0u        // 2 x 38400
#define OFF_AM  76800u    // 2 x 11200 (mask double buffer)
#define OFF_F   99200u    // 400 x 12 floats
#define OFF_H2M 118400u   // 112 x 10 floats
#define OFF_H2S 122880u   // 112 x 10 floats
#define OFF_B2  127360u   // 10 floats
#define SMEM_REQ 127424

__device__ __align__(128) uint8_t g_wq[NB * BNB];    // quantized W1 digits
__device__ float g_c1[HID * CSTRIDE];                // LIF1 carry, transposed [n][m]

struct KeyArr { unsigned a[T_STEPS], b[T_STEPS]; };

// ---------------- threefry2x32 (exact JAX semantics) ----------------
__host__ __device__ __forceinline__ void tfr(unsigned &x0, unsigned &x1, int r){
  x0 += x1;
#ifdef __CUDA_ARCH__
  x1 = __funnelshift_l(x1, x1, r);
#else
  x1 = (x1 << r) | (x1 >> (32 - r));
#endif
  x1 ^= x0;
}
__host__ __device__ __forceinline__ void tf2x32(unsigned k0, unsigned k1,
                                                unsigned x0, unsigned x1,
                                                unsigned &o0, unsigned &o1){
  unsigned k2 = k0 ^ k1 ^ 0x1BD11BDAu;
  x0 += k0; x1 += k1;
  tfr(x0,x1,13); tfr(x0,x1,15); tfr(x0,x1,26); tfr(x0,x1,6);  x0 += k1; x1 += k2 + 1u;
  tfr(x0,x1,17); tfr(x0,x1,29); tfr(x0,x1,16); tfr(x0,x1,24); x0 += k2; x1 += k0 + 2u;
  tfr(x0,x1,13); tfr(x0,x1,15); tfr(x0,x1,26); tfr(x0,x1,6);  x0 += k0; x1 += k1 + 3u;
  tfr(x0,x1,17); tfr(x0,x1,29); tfr(x0,x1,16); tfr(x0,x1,24); x0 += k1; x1 += k2 + 4u;
  tfr(x0,x1,13); tfr(x0,x1,15); tfr(x0,x1,26); tfr(x0,x1,6);  x0 += k2; x1 += k0 + 5u;
  o0 = x0; o1 = x1;
}
__device__ __forceinline__ float tf_u01(unsigned ka, unsigned kb, unsigned i){
  unsigned o0, o1; tf2x32(ka, kb, 0u, i, o0, o1);
  return __uint_as_float((((o0 ^ o1) >> 9) | 0x3f800000u)) - 1.0f;
}

// ---------------- prep: fp32 W1 -> 3 int8 digits (scale 2^24) ----------------
__global__ __launch_bounds__(256) void prep(const float* __restrict__ W1){
  int i = blockIdx.x * 256 + threadIdx.x;
  if (i >= HID * 800) return;
  int n = i / 800, k = i % 800;
  float w = (k < IN_DIM) ? W1[n * IN_DIM + k] : 0.0f;
  int v = __float2int_rn(w * 16777216.0f);          // w * 2^24
  int d0 = ((v & 0xFF) ^ 0x80) - 0x80;  v = (v - d0) >> 8;
  int d1 = ((v & 0xFF) ^ 0x80) - 0x80;  v = (v - d1) >> 8;
  int d2 = v;
  int nb = n / 16, nn = n % 16;
  int kc = k >> 5, kk = k & 31;
  int half = kk >> 4, tig = (kk & 15) >> 2, j = kk & 3;
  unsigned grp = (unsigned)(nn * KC + kc) * 4u + (unsigned)tig;
  uint8_t* base = g_wq + (unsigned)nb * BNB;
  base[grp * 16u + 0u + half * 4u + j]   = (uint8_t)d0;
  base[grp * 16u + 8u + half * 4u + j]   = (uint8_t)d1;
  base[B01SZ + grp * 8u + half * 4u + j] = (uint8_t)d2;
}

// ---------------- device helpers ----------------
__device__ __forceinline__ uint32_t s2u(const void* p){
  uint32_t a; asm("{ .reg .u64 t; cvta.to.shared.u64 t, %1; cvt.u32.u64 %0, t; }" : "=r"(a) : "l"(p));
  return a;
}
__device__ __forceinline__ void imma(int* c, uint32_t a0, uint32_t a1, uint32_t a2,
                                     uint32_t a3, uint32_t b0, uint32_t b1){
  asm volatile("mma.sync.aligned.m16n8k32.row.col.s32.s8.s8.s32 "
               "{%0,%1,%2,%3}, {%4,%5,%6,%7}, {%8,%9}, {%0,%1,%2,%3};"
               : "+r"(c[0]), "+r"(c[1]), "+r"(c[2]), "+r"(c[3])
               : "r"(a0), "r"(a1), "r"(a2), "r"(a3), "r"(b0), "r"(b1));
}
__device__ __forceinline__ void pf_l1(const void* p){
  asm volatile("prefetch.global.L1 [%0];" :: "l"(p));
}
__device__ __forceinline__ void cp_fill(uint8_t* dst, const uint8_t* src, int ctid){
  uint32_t d = s2u(dst);
  for (unsigned ofs = (unsigned)ctid * 16u; ofs < BNB; ofs += 3584u)   // 224 threads
    asm volatile("cp.async.cg.shared.global [%0], [%1], 16;" :: "r"(d + ofs), "l"(src + ofs));
}
__device__ __forceinline__ void bar_cons(){          // consumer-only barrier (224 threads)
  asm volatile("bar.sync 1, 224;" ::: "memory");
}
__device__ __forceinline__ uint32_t gen_word(const float* __restrict__ x,
                                             unsigned ka, unsigned kb, int cta, int w){
  int row = w / 25, wi = w - row * 25;
  int mrow = cta * MT + row;
  if (mrow > B_SZ - 1) mrow = B_SZ - 1;              // pad rows: clamp (results discarded)
  unsigned i0 = (unsigned)mrow * IN_DIM + (unsigned)(wi * 32);
  const float4* xp = (const float4*)(x + i0);
  int QQ = (wi == 24) ? 4 : 8;
  uint32_t word = 0u;
  #pragma unroll 4
  for (int q = 0; q < QQ; q++){
    float4 xv = __ldg(xp + q);
    unsigned ib = i0 + (unsigned)(q * 4);
    word |= (xv.x > tf_u01(ka, kb, ib + 0u)) ? (1u << (q * 4 + 0)) : 0u;
    word |= (xv.y > tf_u01(ka, kb, ib + 1u)) ? (1u << (q * 4 + 1)) : 0u;
    word |= (xv.z > tf_u01(ka, kb, ib + 2u)) ? (1u << (q * 4 + 2)) : 0u;
    word |= (xv.w > tf_u01(ka, kb, ib + 3u)) ? (1u << (q * 4 + 3)) : 0u;
  }
  return word;
}

// ---------------- persistent warp-specialized SNN kernel ----------------
__global__ __launch_bounds__(512, 1) void snn(const float* __restrict__ x,
                                              const float* __restrict__ W2,
                                              const float* __restrict__ b1,
                                              const float* __restrict__ b2,
                                              float* __restrict__ out, KeyArr keys){
  extern __shared__ uint8_t SM[];
  float* Ftab = (float*)(SM + OFF_F);
  float* Sh2m = (float*)(SM + OFF_H2M);
  float* Sh2s = (float*)(SM + OFF_H2S);
  float* Sb2  = (float*)(SM + OFF_B2);
  int tid = threadIdx.x, lane = tid & 31, wid = tid >> 5, cta = blockIdx.x;
  int g = lane >> 2, tig = lane & 3;

  // smem tables (all threads)
  for (int i = tid; i < HID * 12; i += 512){
    int n = i / 12, o = i % 12;
    Ftab[i] = (o < 10) ? W2[o * HID + n] : (o == 10 ? b1[n] : 0.0f);
  }
  for (int i = tid; i < MT * 10; i += 512){ Sh2m[i] = 0.0f; Sh2s[i] = 0.0f; }
  if (tid < 10) Sb2[tid] = b2[tid];

  if (wid >= 7){
    // producers (9 warps): generate masks for t=0
    int ptid = tid - 224;
    unsigned ka = keys.a[0], kb = keys.b[0];
    uint32_t* AMd = (uint32_t*)(SM + OFF_AM);
    #pragma unroll
    for (int j = 0; j < 10; j++){
      int w = ptid + j * 288;
      if (w < NW) AMd[w] = gen_word(x, ka, kb, cta, w);
    }
  } else {
    // consumers (7 warps): prefetch first weight block
    cp_fill(SM + OFF_B, g_wq, tid);
    asm volatile("cp.async.commit_group;" ::: "memory");
  }
  __syncthreads();

  int rA = wid * 16 + g, rB = rA + 8;     // consumer rows (valid for wid<7)
  int mA = cta * MT + rA, mB = mA + 8;
  int gbase = g * 100 + tig;

  for (int t = 0; t < T_STEPS; t++){
    if (wid < 7){
      // ================= consumers =================
      const uint32_t* AMt = (const uint32_t*)(SM + OFF_AM + (unsigned)(t & 1) * (NW * 4u));
      float acc10[2][10] = {};

      for (int nb = 0; nb < NB; nb++){
        int seq = t * NB + nb;
        bar_cons();                       // buffer (seq+1)&1 free
        if (seq + 1 < T_STEPS * NB){
          cp_fill(SM + OFF_B + (unsigned)((seq + 1) & 1) * BNB,
                  g_wq + (unsigned)((nb + 1) % NB) * BNB, tid);
          asm volatile("cp.async.commit_group;" ::: "memory");
          asm volatile("cp.async.wait_group 1;" ::: "memory");
        } else {
          asm volatile("cp.async.wait_group 0;" ::: "memory");
        }
        bar_cons();                       // buffer seq&1 loaded

        // prefetch this block's carry lines into L1 (hidden under the kc loop)
        if (t){
          #pragma unroll
          for (int n8 = 0; n8 < 2; n8++)
            #pragma unroll
            for (int j = 0; j < 2; j++){
              int n = nb * 16 + n8 * 8 + 2 * tig + j;
              pf_l1(g_c1 + (size_t)n * CSTRIDE + mA);
              pf_l1(g_c1 + (size_t)n * CSTRIDE + mB);
            }
        }

        const uint8_t* Bb = SM + OFF_B + (unsigned)(seq & 1) * BNB;
        int accd[6][4] = {};

        #pragma unroll 5
        for (int kc = 0; kc < KC; kc++){
          uint32_t mAv = AMt[rA * 25 + kc], mBv = AMt[rB * 25 + kc];
          uint32_t sa = mAv >> (tig * 4), sb = mBv >> (tig * 4);
          uint32_t a0 = ((sa & 0xFu) * 0x204081u) & 0x01010101u;
          uint32_t a2 = (((sa >> 16) & 0xFu) * 0x204081u) & 0x01010101u;
          uint32_t a1 = ((sb & 0xFu) * 0x204081u) & 0x01010101u;
          uint32_t a3 = (((sb >> 16) & 0xFu) * 0x204081u) & 0x01010101u;
          #pragma unroll
          for (int n8 = 0; n8 < 2; n8++){
            unsigned grp = (unsigned)(n8 * 800 + kc * 4 + gbase);
            uint4 v01 = *(const uint4*)(Bb + grp * 16u);
            uint2 v2  = *(const uint2*)(Bb + B01SZ + grp * 8u);
            imma(accd[n8],     a0, a1, a2, a3, v01.x, v01.y);   // d0
            imma(accd[2 + n8], a0, a1, a2, a3, v01.z, v01.w);   // d1
            imma(accd[4 + n8], a0, a1, a2, a3, v2.x,  v2.y);    // d2
          }
        }

        // epilogue: combine digits -> LIF1 -> GEMM2 partial
        #pragma unroll
        for (int n8 = 0; n8 < 2; n8++){
          #pragma unroll
          for (int j = 0; j < 2; j++){
            int n = nb * 16 + n8 * 8 + 2 * tig + j;
            const float4* Fp = (const float4*)(Ftab + n * 12);
            float4 F0 = Fp[0], F1 = Fp[1], F2 = Fp[2];   // w0..w9, b1 = F2.z
            #pragma unroll
            for (int r = 0; r < 2; r++){
              int ri = r * 2 + j;
              float f = fmaf(__int2float_rn(accd[4 + n8][ri]), 0.00390625f,
                        fmaf(__int2float_rn(accd[2 + n8][ri]), 1.52587890625e-05f,
                             __int2float_rn(accd[n8][ri]) * 5.9604644775390625e-08f));
              int m = r ? mB : mA;
              float* cp_ = g_c1 + (size_t)n * CSTRIDE + m;   // transposed, coalesced
              float carry = t ? *cp_ : 0.0f;
              float mem = (carry + f) + F2.z;
              bool s = mem > 0.5f;
              *cp_ = s ? 0.0f : 0.2f * mem;
              if (s){
                acc10[r][0] += F0.x; acc10[r][1] += F0.y; acc10[r][2] += F0.z; acc10[r][3] += F0.w;
                acc10[r][4] += F1.x; acc10[r][5] += F1.y; acc10[r][6] += F1.z; acc10[r][7] += F1.w;
                acc10[r][8] += F2.x; acc10[r][9] += F2.y;
              }
            }
          }
        }
      }

      // LIF2 + spike-sum update (per row; reduce over 4 tig lanes)
      #pragma unroll
      for (int r = 0; r < 2; r++){
        int rl = r ? rB : rA;
        #pragma unroll
        for (int o = 0; o < 10; o++){
          float v = acc10[r][o];
          v += __shfl_xor_sync(0xffffffffu, v, 1);
          v += __shfl_xor_sync(0xffffffffu, v, 2);
          if (tig == 0){
            float m2 = (Sh2m[rl * 10 + o] + v) + Sb2[o];
            bool s2 = m2 > 0.5f;
            Sh2m[rl * 10 + o] = s2 ? 0.0f : 0.2f * m2;
            Sh2s[rl * 10 + o] += s2 ? 1.0f : 0.0f;
          }
        }
      }
    } else {
      // ================= producers: masks for t+1 =================
      if (t + 1 < T_STEPS){
        int ptid = tid - 224;
        unsigned ka = keys.a[t + 1], kb = keys.b[t + 1];
        uint32_t* AMd = (uint32_t*)(SM + OFF_AM + (unsigned)((t + 1) & 1) * (NW * 4u));
        #pragma unroll
        for (int j = 0; j < 10; j++){
          int w = ptid + j * 288;
          if (w < NW) AMd[w] = gen_word(x, ka, kb, cta, w);
        }
      }
    }
    __syncthreads();
  }

  // output (guard padded rows)
  for (int i = tid; i < MT * 10; i += 512){
    int m = i / 10, o = i % 10;
    int mg = cta * MT + m;
    if (mg < B_SZ) out[mg * 10 + o] = Sh2s[m * 10 + o] * 0.05f;
  }
}

// ---------------- launch ----------------
extern "C" void kernel_launch(void* const* d_in, const int* in_sizes, int n_in,
                              void* d_out, int out_size){
  const float* x  = (const float*)d_in[0];
  const float* W1 = (const float*)d_in[1];
  const float* b1 = (const float*)d_in[2];
  const float* W2 = (const float*)d_in[3];
  const float* b2 = (const float*)d_in[4];
  float* out = (float*)d_out;

  KeyArr keys;
  for (int t = 0; t < T_STEPS; t++){
    unsigned o0, o1;
    tf2x32(0u, 42u, 0u, (unsigned)t, o0, o1);
    keys.a[t] = o0; keys.b[t] = o1;
  }

  cudaFuncSetAttribute(snn, cudaFuncAttributeMaxDynamicSharedMemorySize, SMEM_REQ);
  prep<<<(HID * 800 + 255) / 256, 256>>>(W1);
  snn<<<NCTA, 512, SMEM_REQ>>>(x, W2, b1, b2, out, keys);
}

// round 10
// speedup vs baseline: 1.0599x; 1.0074x over previous
#include <cuda_runtime.h>
#include <cstdint>

#define B_SZ 16384
#define IN_DIM 784
#define HID 400
#define T_STEPS 20
#define NB 25             // n-blocks of 16 columns
#define KC 25             // k-chunks of 32 (K padded 784->800)
#define BNB 38400u        // bytes per n-block (all 3 digits)
#define B01SZ 25600u      // digits 0,1 region within a block
#define APS 816u          // A byte-plane row stride (conflict-free for ldmatrix)
#define OFF_B   0u        // 2 x 38400
#define OFF_AP  76800u    // 128 x 816 byte plane = 104448
#define OFF_AM  181248u   // 3200 mask words (single buffer)
#define OFF_F   194048u   // 400 x 12 floats
#define OFF_H2M 213248u   // 128 x 10 floats
#define OFF_H2S 218368u   // 128 x 10 floats
#define OFF_B2  223488u   // 10 floats
#define SMEM_REQ 223552

__device__ __align__(128) uint8_t g_wq[NB * BNB];  // quantized W1 digits
__device__ float g_c1[HID * B_SZ];                 // LIF1 carry, transposed [n][m]

struct KeyArr { unsigned a[T_STEPS], b[T_STEPS]; };

// ---------------- threefry2x32 (exact JAX semantics) ----------------
__host__ __device__ __forceinline__ void tfr(unsigned &x0, unsigned &x1, int r){
  x0 += x1;
#ifdef __CUDA_ARCH__
  x1 = __funnelshift_l(x1, x1, r);
#else
  x1 = (x1 << r) | (x1 >> (32 - r));
#endif
  x1 ^= x0;
}
__host__ __device__ __forceinline__ void tf2x32(unsigned k0, unsigned k1,
                                                unsigned x0, unsigned x1,
                                                unsigned &o0, unsigned &o1){
  unsigned k2 = k0 ^ k1 ^ 0x1BD11BDAu;
  x0 += k0; x1 += k1;
  tfr(x0,x1,13); tfr(x0,x1,15); tfr(x0,x1,26); tfr(x0,x1,6);  x0 += k1; x1 += k2 + 1u;
  tfr(x0,x1,17); tfr(x0,x1,29); tfr(x0,x1,16); tfr(x0,x1,24); x0 += k2; x1 += k0 + 2u;
  tfr(x0,x1,13); tfr(x0,x1,15); tfr(x0,x1,26); tfr(x0,x1,6);  x0 += k0; x1 += k1 + 3u;
  tfr(x0,x1,17); tfr(x0,x1,29); tfr(x0,x1,16); tfr(x0,x1,24); x0 += k1; x1 += k2 + 4u;
  tfr(x0,x1,13); tfr(x0,x1,15); tfr(x0,x1,26); tfr(x0,x1,6);  x0 += k2; x1 += k0 + 5u;
  o0 = x0; o1 = x1;
}
__device__ __forceinline__ float tf_u01(unsigned ka, unsigned kb, unsigned i){
  unsigned o0, o1; tf2x32(ka, kb, 0u, i, o0, o1);
  return __uint_as_float((((o0 ^ o1) >> 9) | 0x3f800000u)) - 1.0f;
}

// ---------------- prep: fp32 W1 -> 3 int8 digits (scale 2^24) ----------------
__global__ __launch_bounds__(256) void prep(const float* __restrict__ W1){
  int i = blockIdx.x * 256 + threadIdx.x;
  if (i >= HID * 800) return;
  int n = i / 800, k = i % 800;
  float w = (k < IN_DIM) ? W1[n * IN_DIM + k] : 0.0f;
  int v = __float2int_rn(w * 16777216.0f);          // w * 2^24
  int d0 = ((v & 0xFF) ^ 0x80) - 0x80;  v = (v - d0) >> 8;
  int d1 = ((v & 0xFF) ^ 0x80) - 0x80;  v = (v - d1) >> 8;
  int d2 = v;
  int nb = n / 16, nn = n % 16;
  int kc = k >> 5, kk = k & 31;
  int half = kk >> 4, tig = (kk & 15) >> 2, j = kk & 3;
  unsigned grp = (unsigned)(nn * KC + kc) * 4u + (unsigned)tig;
  uint8_t* base = g_wq + (unsigned)nb * BNB;
  base[grp * 16u + 0u + half * 4u + j]   = (uint8_t)d0;
  base[grp * 16u + 8u + half * 4u + j]   = (uint8_t)d1;
  base[B01SZ + grp * 8u + half * 4u + j] = (uint8_t)d2;
}

// ---------------- device helpers ----------------
__device__ __forceinline__ uint32_t s2u(const void* p){
  uint32_t a; asm("{ .reg .u64 t; cvta.to.shared.u64 t, %1; cvt.u32.u64 %0, t; }" : "=r"(a) : "l"(p));
  return a;
}
__device__ __forceinline__ void imma(int* c, uint32_t a0, uint32_t a1, uint32_t a2,
                                     uint32_t a3, uint32_t b0, uint32_t b1){
  asm volatile("mma.sync.aligned.m16n8k32.row.col.s32.s8.s8.s32 "
               "{%0,%1,%2,%3}, {%4,%5,%6,%7}, {%8,%9}, {%0,%1,%2,%3};"
               : "+r"(c[0]), "+r"(c[1]), "+r"(c[2]), "+r"(c[3])
               : "r"(a0), "r"(a1), "r"(a2), "r"(a3), "r"(b0), "r"(b1));
}
__device__ __forceinline__ void ldmA(uint32_t* a, uint32_t addr){
  asm volatile("ldmatrix.sync.aligned.m8n8.x4.shared.b16 {%0,%1,%2,%3}, [%4];"
               : "=r"(a[0]), "=r"(a[1]), "=r"(a[2]), "=r"(a[3]) : "r"(addr));
}
__device__ __forceinline__ void cp_fill(uint8_t* dst, const uint8_t* src, int ctid){
  uint32_t d = s2u(dst);
  for (unsigned ofs = (unsigned)ctid * 16u; ofs < BNB; ofs += 4096u)   // 256 threads
    asm volatile("cp.async.cg.shared.global [%0], [%1], 16;" :: "r"(d + ofs), "l"(src + ofs));
}
__device__ __forceinline__ void bar_cons(){          // consumer-only barrier (256 threads)
  asm volatile("bar.sync 1, 256;" ::: "memory");
}
__device__ __forceinline__ uint32_t gen_word(const float* __restrict__ x,
                                             unsigned ka, unsigned kb, int cta, int w){
  int row = w / 25, wi = w - row * 25;
  unsigned i0 = (unsigned)(cta * 128 + row) * IN_DIM + (unsigned)(wi * 32);
  const float4* xp = (const float4*)(x + i0);
  int QQ = (wi == 24) ? 4 : 8;
  uint32_t word = 0u;
  #pragma unroll 4
  for (int q = 0; q < QQ; q++){
    float4 xv = __ldg(xp + q);
    unsigned ib = i0 + (unsigned)(q * 4);
    word |= (xv.x > tf_u01(ka, kb, ib + 0u)) ? (1u << (q * 4 + 0)) : 0u;
    word |= (xv.y > tf_u01(ka, kb, ib + 1u)) ? (1u << (q * 4 + 1)) : 0u;
    word |= (xv.z > tf_u01(ka, kb, ib + 2u)) ? (1u << (q * 4 + 2)) : 0u;
    word |= (xv.w > tf_u01(ka, kb, ib + 3u)) ? (1u << (q * 4 + 3)) : 0u;
  }
  return word;
}

// ---------------- persistent warp-specialized SNN kernel ----------------
__global__ __launch_bounds__(512, 1) void snn(const float* __restrict__ x,
                                              const float* __restrict__ W2,
                                              const float* __restrict__ b1,
                                              const float* __restrict__ b2,
                                              float* __restrict__ out, KeyArr keys){
  extern __shared__ uint8_t SM[];
  float* Ftab = (float*)(SM + OFF_F);
  float* Sh2m = (float*)(SM + OFF_H2M);
  float* Sh2s = (float*)(SM + OFF_H2S);
  float* Sb2  = (float*)(SM + OFF_B2);
  uint32_t* AM = (uint32_t*)(SM + OFF_AM);
  uint32_t SB = s2u(SM);
  int tid = threadIdx.x, lane = tid & 31, wid = tid >> 5, cta = blockIdx.x;
  int g = lane >> 2, tig = lane & 3;

  // smem tables (all threads)
  for (int i = tid; i < HID * 12; i += 512){
    int n = i / 12, o = i % 12;
    Ftab[i] = (o < 10) ? W2[o * HID + n] : (o == 10 ? b1[n] : 0.0f);
  }
  for (int i = tid; i < 1280; i += 512){ Sh2m[i] = 0.0f; Sh2s[i] = 0.0f; }
  if (tid < 10) Sb2[tid] = b2[tid];

  if (wid >= 8){
    // producers: generate masks for t=0
    int ptid = tid - 256;
    unsigned ka = keys.a[0], kb = keys.b[0];
    #pragma unroll
    for (int j = 0; j < 13; j++){
      int w = ptid + (j << 8);
      if (w < 3200) AM[w] = gen_word(x, ka, kb, cta, w);
    }
  } else {
    // consumers: prefetch first weight block
    cp_fill(SM + OFF_B, g_wq, tid);
    asm volatile("cp.async.commit_group;" ::: "memory");
  }

  int rA = wid * 16 + g, rB = rA + 8;     // consumer rows (valid for wid<8)
  int mA = cta * 128 + rA, mB = mA + 8;
  int gbase = g * 100 + tig;
  // per-lane ldmatrix base address for this warp's 16x32 A tile
  uint32_t apbase = SB + OFF_AP
                  + (unsigned)(wid * 16 + ((lane >> 3) & 1) * 8 + (lane & 7)) * APS
                  + ((lane >> 4) & 1 ? 16u : 0u);

  for (int t = 0; t < T_STEPS; t++){
    __syncthreads();                      // masks(t) ready; plane(t-1) fully consumed
    // ---- expand masks -> s8 byte plane (all 512 threads, ~0.5k cyc) ----
    for (int w = tid; w < 3200; w += 512){
      int row = w / 25, wi = w - row * 25;
      uint32_t word = AM[w];
      uint8_t* dst = SM + OFF_AP + (unsigned)row * APS + (unsigned)wi * 32u;
      uint4 v;
      v.x = ((word       ) & 0xFu) * 0x204081u & 0x01010101u;
      v.y = ((word >>  4u) & 0xFu) * 0x204081u & 0x01010101u;
      v.z = ((word >>  8u) & 0xFu) * 0x204081u & 0x01010101u;
      v.w = ((word >> 12u) & 0xFu) * 0x204081u & 0x01010101u;
      *(uint4*)dst = v;
      v.x = ((word >> 16u) & 0xFu) * 0x204081u & 0x01010101u;
      v.y = ((word >> 20u) & 0xFu) * 0x204081u & 0x01010101u;
      v.z = ((word >> 24u) & 0xFu) * 0x204081u & 0x01010101u;
      v.w = ((word >> 28u) & 0xFu) * 0x204081u & 0x01010101u;
      *(uint4*)(dst + 16) = v;
    }
    __syncthreads();                      // plane ready; AM free for t+1

    if (wid < 8){
      // ================= consumers =================
      float acc10[2][10] = {};

      for (int nb = 0; nb < NB; nb++){
        int seq = t * NB + nb;
        bar_cons();                       // buffer (seq+1)&1 free
        if (seq + 1 < T_STEPS * NB){
          cp_fill(SM + OFF_B + (unsigned)((seq + 1) & 1) * BNB,
                  g_wq + (unsigned)((nb + 1) % NB) * BNB, tid);
          asm volatile("cp.async.commit_group;" ::: "memory");
          asm volatile("cp.async.wait_group 1;" ::: "memory");
        } else {
          asm volatile("cp.async.wait_group 0;" ::: "memory");
        }
        bar_cons();                       // buffer seq&1 loaded

        const uint8_t* Bb = SM + OFF_B + (unsigned)(seq & 1) * BNB;
        int accd[6][4] = {};

        #pragma unroll 5
        for (int kc = 0; kc < KC; kc++){
          uint32_t a[4];
          ldmA(a, apbase + (unsigned)kc * 32u);
          #pragma unroll
          for (int n8 = 0; n8 < 2; n8++){
            unsigned grp = (unsigned)(n8 * 800 + kc * 4 + gbase);
            uint4 v01 = *(const uint4*)(Bb + grp * 16u);
            uint2 v2  = *(const uint2*)(Bb + B01SZ + grp * 8u);
            imma(accd[n8],     a[0], a[1], a[2], a[3], v01.x, v01.y);   // d0
            imma(accd[2 + n8], a[0], a[1], a[2], a[3], v01.z, v01.w);   // d1
            imma(accd[4 + n8], a[0], a[1], a[2], a[3], v2.x,  v2.y);    // d2
          }
        }

        // epilogue: combine digits -> LIF1 -> GEMM2 partial
        #pragma unroll
        for (int n8 = 0; n8 < 2; n8++){
          #pragma unroll
          for (int j = 0; j < 2; j++){
            int n = nb * 16 + n8 * 8 + 2 * tig + j;
            const float4* Fp = (const float4*)(Ftab + n * 12);
            float4 F0 = Fp[0], F1 = Fp[1], F2 = Fp[2];   // w0..w9, b1 = F2.z
            #pragma unroll
            for (int r = 0; r < 2; r++){
              int ri = r * 2 + j;
              float f = fmaf(__int2float_rn(accd[4 + n8][ri]), 0.00390625f,
                        fmaf(__int2float_rn(accd[2 + n8][ri]), 1.52587890625e-05f,
                             __int2float_rn(accd[n8][ri]) * 5.9604644775390625e-08f));
              int m = r ? mB : mA;
              float* cp_ = g_c1 + (size_t)n * B_SZ + m;    // transposed, coalesced
              float carry = t ? *cp_ : 0.0f;
              float mem = (carry + f) + F2.z;
              bool s = mem > 0.5f;
              *cp_ = s ? 0.0f : 0.2f * mem;
              if (s){
                acc10[r][0] += F0.x; acc10[r][1] += F0.y; acc10[r][2] += F0.z; acc10[r][3] += F0.w;
                acc10[r][4] += F1.x; acc10[r][5] += F1.y; acc10[r][6] += F1.z; acc10[r][7] += F1.w;
                acc10[r][8] += F2.x; acc10[r][9] += F2.y;
              }
            }
          }
        }
      }

      // LIF2 + spike-sum update (per row; reduce over 4 tig lanes)
      #pragma unroll
      for (int r = 0; r < 2; r++){
        int rl = r ? rB : rA;
        #pragma unroll
        for (int o = 0; o < 10; o++){
          float v = acc10[r][o];
          v += __shfl_xor_sync(0xffffffffu, v, 1);
          v += __shfl_xor_sync(0xffffffffu, v, 2);
          if (tig == 0){
            float m2 = (Sh2m[rl * 10 + o] + v) + Sb2[o];
            bool s2 = m2 > 0.5f;
            Sh2m[rl * 10 + o] = s2 ? 0.0f : 0.2f * m2;
            Sh2s[rl * 10 + o] += s2 ? 1.0f : 0.0f;
          }
        }
      }
    } else {
      // ================= producers: masks for t+1 =================
      if (t + 1 < T_STEPS){
        int ptid = tid - 256;
        unsigned ka = keys.a[t + 1], kb = keys.b[t + 1];
        #pragma unroll
        for (int j = 0; j < 13; j++){
          int w = ptid + (j << 8);
          if (w < 3200) AM[w] = gen_word(x, ka, kb, cta, w);
        }
      }
    }
  }
  __syncthreads();

  // output
  for (int i = tid; i < 1280; i += 512){
    int m = i / 10, o = i % 10;
    out[(cta * 128 + m) * 10 + o] = Sh2s[m * 10 + o] * 0.05f;
  }
}

// ---------------- launch ----------------
extern "C" void kernel_launch(void* const* d_in, const int* in_sizes, int n_in,
                              void* d_out, int out_size){
  const float* x  = (const float*)d_in[0];
  const float* W1 = (const float*)d_in[1];
  const float* b1 = (const float*)d_in[2];
  const float* W2 = (const float*)d_in[3];
  const float* b2 = (const float*)d_in[4];
  float* out = (float*)d_out;

  KeyArr keys;
  for (int t = 0; t < T_STEPS; t++){
    unsigned o0, o1;
    tf2x32(0u, 42u, 0u, (unsigned)t, o0, o1);
    keys.a[t] = o0; keys.b[t] = o1;
  }

  cudaFuncSetAttribute(snn, cudaFuncAttributeMaxDynamicSharedMemorySize, SMEM_REQ);
  prep<<<(HID * 800 + 255) / 256, 256>>>(W1);
  snn<<<128, 512, SMEM_REQ>>>(x, W2, b1, b2, out, keys);
}

// round 11
// speedup vs baseline: 1.0850x; 1.0237x over previous
#include <cuda_runtime.h>
#include <cstdint>

#define B_SZ 16384
#define IN_DIM 784
#define HID 400
#define T_STEPS 20
#define NB 25             // n-blocks of 16 columns
#define KC 25             // k-chunks of 32 (K padded 784->800)
#define NSEQ (T_STEPS*NB) // 500
#define BNB 38400u        // bytes per n-block (all 3 digits)
#define B01SZ 25600u      // digits 0,1 region within a block
#define OFF_B   0u        // 3 x 38400 ring
#define OFF_AM  115200u   // 2 x 12800 mask double buffer
#define OFF_F   140800u   // 400 x 12 floats
#define OFF_H2M 160000u   // 128 x 10 floats
#define OFF_H2S 165120u   // 128 x 10 floats
#define OFF_B2  170240u
#define OFF_MB  170304u   // full[3] @ +0,+8,+16 ; empty[3] @ +24,+32,+40
#define SMEM_REQ 170368

__device__ __align__(128) uint8_t g_wq[NB * BNB];  // quantized W1 digits
__device__ float g_c1[HID * B_SZ];                 // LIF1 carry, transposed [n][m]

struct KeyArr { unsigned a[T_STEPS], b[T_STEPS]; };

// ---------------- threefry2x32 (exact JAX semantics) ----------------
__host__ __device__ __forceinline__ void tfr(unsigned &x0, unsigned &x1, int r){
  x0 += x1;
#ifdef __CUDA_ARCH__
  x1 = __funnelshift_l(x1, x1, r);
#else
  x1 = (x1 << r) | (x1 >> (32 - r));
#endif
  x1 ^= x0;
}
__host__ __device__ __forceinline__ void tf2x32(unsigned k0, unsigned k1,
                                                unsigned x0, unsigned x1,
                                                unsigned &o0, unsigned &o1){
  unsigned k2 = k0 ^ k1 ^ 0x1BD11BDAu;
  x0 += k0; x1 += k1;
  tfr(x0,x1,13); tfr(x0,x1,15); tfr(x0,x1,26); tfr(x0,x1,6);  x0 += k1; x1 += k2 + 1u;
  tfr(x0,x1,17); tfr(x0,x1,29); tfr(x0,x1,16); tfr(x0,x1,24); x0 += k2; x1 += k0 + 2u;
  tfr(x0,x1,13); tfr(x0,x1,15); tfr(x0,x1,26); tfr(x0,x1,6);  x0 += k0; x1 += k1 + 3u;
  tfr(x0,x1,17); tfr(x0,x1,29); tfr(x0,x1,16); tfr(x0,x1,24); x0 += k1; x1 += k2 + 4u;
  tfr(x0,x1,13); tfr(x0,x1,15); tfr(x0,x1,26); tfr(x0,x1,6);  x0 += k2; x1 += k0 + 5u;
  o0 = x0; o1 = x1;
}
__device__ __forceinline__ float tf_u01(unsigned ka, unsigned kb, unsigned i){
  unsigned o0, o1; tf2x32(ka, kb, 0u, i, o0, o1);
  return __uint_as_float((((o0 ^ o1) >> 9) | 0x3f800000u)) - 1.0f;
}

// ---------------- prep: fp32 W1 -> 3 int8 digits (scale 2^24) ----------------
__global__ __launch_bounds__(256) void prep(const float* __restrict__ W1){
  int i = blockIdx.x * 256 + threadIdx.x;
  if (i >= HID * 800) return;
  int n = i / 800, k = i % 800;
  float w = (k < IN_DIM) ? W1[n * IN_DIM + k] : 0.0f;
  int v = __float2int_rn(w * 16777216.0f);          // w * 2^24
  int d0 = ((v & 0xFF) ^ 0x80) - 0x80;  v = (v - d0) >> 8;
  int d1 = ((v & 0xFF) ^ 0x80) - 0x80;  v = (v - d1) >> 8;
  int d2 = v;
  int nb = n / 16, nn = n % 16;
  int kc = k >> 5, kk = k & 31;
  int half = kk >> 4, tig = (kk & 15) >> 2, j = kk & 3;
  unsigned grp = (unsigned)(nn * KC + kc) * 4u + (unsigned)tig;
  uint8_t* base = g_wq + (unsigned)nb * BNB;
  base[grp * 16u + 0u + half * 4u + j]   = (uint8_t)d0;
  base[grp * 16u + 8u + half * 4u + j]   = (uint8_t)d1;
  base[B01SZ + grp * 8u + half * 4u + j] = (uint8_t)d2;
}

// ---------------- device helpers ----------------
__device__ __forceinline__ uint32_t s2u(const void* p){
  uint32_t a; asm("{ .reg .u64 t; cvta.to.shared.u64 t, %1; cvt.u32.u64 %0, t; }" : "=r"(a) : "l"(p));
  return a;
}
__device__ __forceinline__ void imma(int* c, uint32_t a0, uint32_t a1, uint32_t a2,
                                     uint32_t a3, uint32_t b0, uint32_t b1){
  asm volatile("mma.sync.aligned.m16n8k32.row.col.s32.s8.s8.s32 "
               "{%0,%1,%2,%3}, {%4,%5,%6,%7}, {%8,%9}, {%0,%1,%2,%3};"
               : "+r"(c[0]), "+r"(c[1]), "+r"(c[2]), "+r"(c[3])
               : "r"(a0), "r"(a1), "r"(a2), "r"(a3), "r"(b0), "r"(b1));
}
__device__ __forceinline__ void mbar_init(uint32_t mb, uint32_t n){
  asm volatile("mbarrier.init.shared.b64 [%0], %1;" :: "r"(mb), "r"(n) : "memory");
}
__device__ __forceinline__ void mbar_expect(uint32_t mb, uint32_t bytes){
  asm volatile("mbarrier.arrive.expect_tx.shared.b64 _, [%0], %1;" :: "r"(mb), "r"(bytes) : "memory");
}
__device__ __forceinline__ void mbar_arrive(uint32_t mb){
  asm volatile("mbarrier.arrive.shared.b64 _, [%0];" :: "r"(mb) : "memory");
}
__device__ __forceinline__ void mbar_wait(uint32_t mb, uint32_t ph){
  asm volatile("{ .reg .pred P; W_%=:\n\t"
    "mbarrier.try_wait.parity.acquire.cta.shared::cta.b64 P, [%0], %1, 0x989680;\n\t"
    "@!P bra W_%=; }" :: "r"(mb), "r"(ph) : "memory");
}
__device__ __forceinline__ void bulkcp(uint32_t dst, const void* src, uint32_t mb){
  asm volatile("cp.async.bulk.shared::cluster.global.mbarrier::complete_tx::bytes [%0], [%1], %2, [%3];"
    :: "r"(dst), "l"(src), "r"(BNB), "r"(mb) : "memory");
}
__device__ __forceinline__ void bar15(){   // warps 0..14 (480 threads)
  asm volatile("bar.sync 1, 480;" ::: "memory");
}
__device__ __forceinline__ uint32_t gen_word(const float* __restrict__ x,
                                             unsigned ka, unsigned kb, int cta, int w){
  int row = w / 25, wi = w - row * 25;
  unsigned i0 = (unsigned)(cta * 128 + row) * IN_DIM + (unsigned)(wi * 32);
  const float4* xp = (const float4*)(x + i0);
  int QQ = (wi == 24) ? 4 : 8;
  uint32_t word = 0u;
  #pragma unroll 4
  for (int q = 0; q < QQ; q++){
    float4 xv = __ldg(xp + q);
    unsigned ib = i0 + (unsigned)(q * 4);
    word |= (xv.x > tf_u01(ka, kb, ib + 0u)) ? (1u << (q * 4 + 0)) : 0u;
    word |= (xv.y > tf_u01(ka, kb, ib + 1u)) ? (1u << (q * 4 + 1)) : 0u;
    word |= (xv.z > tf_u01(ka, kb, ib + 2u)) ? (1u << (q * 4 + 2)) : 0u;
    word |= (xv.w > tf_u01(ka, kb, ib + 3u)) ? (1u << (q * 4 + 3)) : 0u;
  }
  return word;
}

// ---------------- persistent SNN kernel: decoupled warps ----------------
__global__ __launch_bounds__(512, 1) void snn(const float* __restrict__ x,
                                              const float* __restrict__ W2,
                                              const float* __restrict__ b1,
                                              const float* __restrict__ b2,
                                              float* __restrict__ out, KeyArr keys){
  extern __shared__ uint8_t SM[];
  float* Ftab = (float*)(SM + OFF_F);
  float* Sh2m = (float*)(SM + OFF_H2M);
  float* Sh2s = (float*)(SM + OFF_H2S);
  float* Sb2  = (float*)(SM + OFF_B2);
  uint32_t SB = s2u(SM);
  uint32_t mFull = SB + OFF_MB, mEmpty = SB + OFF_MB + 24;
  int tid = threadIdx.x, lane = tid & 31, wid = tid >> 5, cta = blockIdx.x;
  int g = lane >> 2, tig = lane & 3;

  // smem tables (all threads)
  for (int i = tid; i < HID * 12; i += 512){
    int n = i / 12, o = i % 12;
    Ftab[i] = (o < 10) ? W2[o * HID + n] : (o == 10 ? b1[n] : 0.0f);
  }
  for (int i = tid; i < 1280; i += 512){ Sh2m[i] = 0.0f; Sh2s[i] = 0.0f; }
  if (tid < 10) Sb2[tid] = b2[tid];
  if (tid == 0){
    #pragma unroll
    for (int s = 0; s < 3; s++){ mbar_init(mFull + s * 8, 1); mbar_init(mEmpty + s * 8, 8); }
  }
  __syncthreads();                        // tables + mbarriers visible

  if (wid == 15){
    // ================= filler warp: weight ring service =================
    if (lane == 0){
      for (int f = 0; f < NSEQ; f++){
        int s = f - (f / 3) * 3;
        if (f >= 3){
          mbar_wait(mEmpty + s * 8, (uint32_t)((f / 3 - 1) & 1));
        }
        mbar_expect(mFull + s * 8, BNB);
        bulkcp(SB + OFF_B + (unsigned)s * BNB, g_wq + (unsigned)(f % NB) * BNB, mFull + s * 8);
      }
    }
  } else if (wid >= 8){
    // ================= producers (7 warps): spike masks =================
    int ptid = tid - 256;                  // 0..223
    {
      unsigned ka = keys.a[0], kb = keys.b[0];
      uint32_t* AMd = (uint32_t*)(SM + OFF_AM);
      #pragma unroll
      for (int j = 0; j < 15; j++){
        int w = ptid + j * 224;
        if (w < 3200) AMd[w] = gen_word(x, ka, kb, cta, w);
      }
    }
    bar15();                               // AM(t=0) ready
    for (int t = 0; t < T_STEPS; t++){
      if (t + 1 < T_STEPS){
        unsigned ka = keys.a[t + 1], kb = keys.b[t + 1];
        uint32_t* AMd = (uint32_t*)(SM + OFF_AM + (unsigned)((t + 1) & 1) * 12800u);
        #pragma unroll
        for (int j = 0; j < 15; j++){
          int w = ptid + j * 224;
          if (w < 3200) AMd[w] = gen_word(x, ka, kb, cta, w);
        }
      }
      bar15();
    }
  } else {
    // ================= consumers (8 warps) =================
    int rA = wid * 16 + g, rB = rA + 8;
    int mA = cta * 128 + rA, mB = mA + 8;
    int gbase = g * 100 + tig;
    bar15();                               // wait AM(t=0)

    for (int t = 0; t < T_STEPS; t++){
      const uint32_t* AMt = (const uint32_t*)(SM + OFF_AM + (unsigned)(t & 1) * 12800u);
      float acc10[2][10] = {};

      for (int nb = 0; nb < NB; nb++){
        int seq = t * NB + nb;
        int s = seq - (seq / 3) * 3;
        mbar_wait(mFull + s * 8, (uint32_t)((seq / 3) & 1));   // weights(seq) in slot s

        const uint8_t* Bb = SM + OFF_B + (unsigned)s * BNB;
        int accd[6][4] = {};

        #pragma unroll 5
        for (int kc = 0; kc < KC; kc++){
          uint32_t mAv = AMt[rA * 25 + kc], mBv = AMt[rB * 25 + kc];
          uint32_t sa = mAv >> (tig * 4), sb = mBv >> (tig * 4);
          uint32_t a0 = ((sa & 0xFu) * 0x204081u) & 0x01010101u;
          uint32_t a2 = (((sa >> 16) & 0xFu) * 0x204081u) & 0x01010101u;
          uint32_t a1 = ((sb & 0xFu) * 0x204081u) & 0x01010101u;
          uint32_t a3 = (((sb >> 16) & 0xFu) * 0x204081u) & 0x01010101u;
          #pragma unroll
          for (int n8 = 0; n8 < 2; n8++){
            unsigned grp = (unsigned)(n8 * 800 + kc * 4 + gbase);
            uint4 v01 = *(const uint4*)(Bb + grp * 16u);
            uint2 v2  = *(const uint2*)(Bb + B01SZ + grp * 8u);
            imma(accd[n8],     a0, a1, a2, a3, v01.x, v01.y);   // d0
            imma(accd[2 + n8], a0, a1, a2, a3, v01.z, v01.w);   // d1
            imma(accd[4 + n8], a0, a1, a2, a3, v2.x,  v2.y);    // d2
          }
        }
        __syncwarp();
        if (lane == 0) mbar_arrive(mEmpty + s * 8);   // done reading slot s

        // epilogue: combine digits -> LIF1 -> GEMM2 partial (overlaps other warps' mma)
        #pragma unroll
        for (int n8 = 0; n8 < 2; n8++){
          #pragma unroll
          for (int j = 0; j < 2; j++){
            int n = nb * 16 + n8 * 8 + 2 * tig + j;
            const float4* Fp = (const float4*)(Ftab + n * 12);
            float4 F0 = Fp[0], F1 = Fp[1], F2 = Fp[2];   // w0..w9, b1 = F2.z
            #pragma unroll
            for (int r = 0; r < 2; r++){
              int ri = r * 2 + j;
              float f = fmaf(__int2float_rn(accd[4 + n8][ri]), 0.00390625f,
                        fmaf(__int2float_rn(accd[2 + n8][ri]), 1.52587890625e-05f,
                             __int2float_rn(accd[n8][ri]) * 5.9604644775390625e-08f));
              int m = r ? mB : mA;
              float* cp_ = g_c1 + (size_t)n * B_SZ + m;
              float carry = t ? *cp_ : 0.0f;
              float mem = (carry + f) + F2.z;
              bool sgn = mem > 0.5f;
              *cp_ = sgn ? 0.0f : 0.2f * mem;
              if (sgn){
                acc10[r][0] += F0.x; acc10[r][1] += F0.y; acc10[r][2] += F0.z; acc10[r][3] += F0.w;
                acc10[r][4] += F1.x; acc10[r][5] += F1.y; acc10[r][6] += F1.z; acc10[r][7] += F1.w;
                acc10[r][8] += F2.x; acc10[r][9] += F2.y;
              }
            }
          }
        }
      }

      // LIF2 + spike-sum update (per row; reduce over 4 tig lanes)
      #pragma unroll
      for (int r = 0; r < 2; r++){
        int rl = r ? rB : rA;
        #pragma unroll
        for (int o = 0; o < 10; o++){
          float v = acc10[r][o];
          v += __shfl_xor_sync(0xffffffffu, v, 1);
          v += __shfl_xor_sync(0xffffffffu, v, 2);
          if (tig == 0){
            float m2 = (Sh2m[rl * 10 + o] + v) + Sb2[o];
            bool s2 = m2 > 0.5f;
            Sh2m[rl * 10 + o] = s2 ? 0.0f : 0.2f * m2;
            Sh2s[rl * 10 + o] += s2 ? 1.0f : 0.0f;
          }
        }
      }
      bar15();
    }
  }
  __syncthreads();

  // output
  for (int i = tid; i < 1280; i += 512){
    int m = i / 10, o = i % 10;
    out[(cta * 128 + m) * 10 + o] = Sh2s[m * 10 + o] * 0.05f;
  }
}

// ---------------- launch ----------------
extern "C" void kernel_launch(void* const* d_in, const int* in_sizes, int n_in,
                              void* d_out, int out_size){
  const float* x  = (const float*)d_in[0];
  const float* W1 = (const float*)d_in[1];
  const float* b1 = (const float*)d_in[2];
  const float* W2 = (const float*)d_in[3];
  const float* b2 = (const float*)d_in[4];
  float* out = (float*)d_out;

  KeyArr keys;
  for (int t = 0; t < T_STEPS; t++){
    unsigned o0, o1;
    tf2x32(0u, 42u, 0u, (unsigned)t, o0, o1);
    keys.a[t] = o0; keys.b[t] = o1;
  }

  cudaFuncSetAttribute(snn, cudaFuncAttributeMaxDynamicSharedMemorySize, SMEM_REQ);
  prep<<<(HID * 800 + 255) / 256, 256>>>(W1);
  snn<<<128, 512, SMEM_REQ>>>(x, W2, b1, b2, out, keys);
}

// round 12
// speedup vs baseline: 1.1162x; 1.0288x over previous
#include <cuda_runtime.h>
#include <cstdint>

#define B_SZ 16384
#define IN_DIM 784
#define HID 400
#define T_STEPS 20
#define NB 25             // n-blocks of 16 columns
#define KC 25             // k-chunks of 32 (K padded 784->800)
#define NSEQ (T_STEPS*NB) // 500
#define BNB 38400u        // bytes per n-block (all 3 digits)
#define B01SZ 25600u      // digits 0,1 region within a block
#define OFF_B   0u        // 4 x 38400 ring = 153600
#define OFF_AM  153600u   // 2 x 12800 mask double buffer
#define OFF_F   179200u   // 400 x 12 floats
#define OFF_H2M 198400u   // 128 x 10 floats
#define OFF_H2S 203520u   // 128 x 10 floats
#define OFF_B2  208640u
#define OFF_MB  208704u   // full[4] @ +0..+24 ; empty[4] @ +32..+56
#define SMEM_REQ 208832

__device__ __align__(128) uint8_t g_wq[NB * BNB];  // quantized W1 digits
__device__ float g_c1[HID * B_SZ];                 // LIF1 carry, transposed [n][m]

struct KeyArr { unsigned a[T_STEPS], b[T_STEPS]; };

// ---------------- threefry2x32 (exact JAX semantics) ----------------
__host__ __device__ __forceinline__ void tfr(unsigned &x0, unsigned &x1, int r){
  x0 += x1;
#ifdef __CUDA_ARCH__
  x1 = __funnelshift_l(x1, x1, r);
#else
  x1 = (x1 << r) | (x1 >> (32 - r));
#endif
  x1 ^= x0;
}
__host__ __device__ __forceinline__ void tf2x32(unsigned k0, unsigned k1,
                                                unsigned x0, unsigned x1,
                                                unsigned &o0, unsigned &o1){
  unsigned k2 = k0 ^ k1 ^ 0x1BD11BDAu;
  x0 += k0; x1 += k1;
  tfr(x0,x1,13); tfr(x0,x1,15); tfr(x0,x1,26); tfr(x0,x1,6);  x0 += k1; x1 += k2 + 1u;
  tfr(x0,x1,17); tfr(x0,x1,29); tfr(x0,x1,16); tfr(x0,x1,24); x0 += k2; x1 += k0 + 2u;
  tfr(x0,x1,13); tfr(x0,x1,15); tfr(x0,x1,26); tfr(x0,x1,6);  x0 += k0; x1 += k1 + 3u;
  tfr(x0,x1,17); tfr(x0,x1,29); tfr(x0,x1,16); tfr(x0,x1,24); x0 += k1; x1 += k2 + 4u;
  tfr(x0,x1,13); tfr(x0,x1,15); tfr(x0,x1,26); tfr(x0,x1,6);  x0 += k2; x1 += k0 + 5u;
  o0 = x0; o1 = x1;
}
__device__ __forceinline__ float tf_u01(unsigned ka, unsigned kb, unsigned i){
  unsigned o0, o1; tf2x32(ka, kb, 0u, i, o0, o1);
  return __uint_as_float((((o0 ^ o1) >> 9) | 0x3f800000u)) - 1.0f;
}

// ---------------- prep: fp32 W1 -> 3 int8 digits (scale 2^24) ----------------
__global__ __launch_bounds__(256) void prep(const float* __restrict__ W1){
  int i = blockIdx.x * 256 + threadIdx.x;
  if (i >= HID * 800) return;
  int n = i / 800, k = i % 800;
  float w = (k < IN_DIM) ? W1[n * IN_DIM + k] : 0.0f;
  int v = __float2int_rn(w * 16777216.0f);          // w * 2^24
  int d0 = ((v & 0xFF) ^ 0x80) - 0x80;  v = (v - d0) >> 8;
  int d1 = ((v & 0xFF) ^ 0x80) - 0x80;  v = (v - d1) >> 8;
  int d2 = v;
  int nb = n / 16, nn = n % 16;
  int kc = k >> 5, kk = k & 31;
  int half = kk >> 4, tig = (kk & 15) >> 2, j = kk & 3;
  unsigned grp = (unsigned)(nn * KC + kc) * 4u + (unsigned)tig;
  uint8_t* base = g_wq + (unsigned)nb * BNB;
  base[grp * 16u + 0u + half * 4u + j]   = (uint8_t)d0;
  base[grp * 16u + 8u + half * 4u + j]   = (uint8_t)d1;
  base[B01SZ + grp * 8u + half * 4u + j] = (uint8_t)d2;
}

// ---------------- device helpers ----------------
__device__ __forceinline__ uint32_t s2u(const void* p){
  uint32_t a; asm("{ .reg .u64 t; cvta.to.shared.u64 t, %1; cvt.u32.u64 %0, t; }" : "=r"(a) : "l"(p));
  return a;
}
__device__ __forceinline__ void imma(int* c, uint32_t a0, uint32_t a1, uint32_t a2,
                                     uint32_t a3, uint32_t b0, uint32_t b1){
  asm volatile("mma.sync.aligned.m16n8k32.row.col.s32.s8.s8.s32 "
               "{%0,%1,%2,%3}, {%4,%5,%6,%7}, {%8,%9}, {%0,%1,%2,%3};"
               : "+r"(c[0]), "+r"(c[1]), "+r"(c[2]), "+r"(c[3])
               : "r"(a0), "r"(a1), "r"(a2), "r"(a3), "r"(b0), "r"(b1));
}
__device__ __forceinline__ void mbar_init(uint32_t mb, uint32_t n){
  asm volatile("mbarrier.init.shared.b64 [%0], %1;" :: "r"(mb), "r"(n) : "memory");
}
__device__ __forceinline__ void mbar_expect(uint32_t mb, uint32_t bytes){
  asm volatile("mbarrier.arrive.expect_tx.shared.b64 _, [%0], %1;" :: "r"(mb), "r"(bytes) : "memory");
}
__device__ __forceinline__ void mbar_arrive(uint32_t mb){
  asm volatile("mbarrier.arrive.shared.b64 _, [%0];" :: "r"(mb) : "memory");
}
__device__ __forceinline__ void mbar_wait(uint32_t mb, uint32_t ph){
  asm volatile("{ .reg .pred P; W_%=:\n\t"
    "mbarrier.try_wait.parity.acquire.cta.shared::cta.b64 P, [%0], %1, 0x989680;\n\t"
    "@!P bra W_%=; }" :: "r"(mb), "r"(ph) : "memory");
}
__device__ __forceinline__ void bulkcp(uint32_t dst, const void* src, uint32_t mb){
  asm volatile("cp.async.bulk.shared::cluster.global.mbarrier::complete_tx::bytes [%0], [%1], %2, [%3];"
    :: "r"(dst), "l"(src), "r"(BNB), "r"(mb) : "memory");
}
__device__ __forceinline__ void bar11(){   // warps 0..10 (352 threads): consumers + producers
  asm volatile("bar.sync 1, 352;" ::: "memory");
}
__device__ __forceinline__ uint32_t gen_word(const float* __restrict__ x,
                                             unsigned ka, unsigned kb, int cta, int w){
  int row = w / 25, wi = w - row * 25;
  unsigned i0 = (unsigned)(cta * 128 + row) * IN_DIM + (unsigned)(wi * 32);
  const float4* xp = (const float4*)(x + i0);
  int QQ = (wi == 24) ? 4 : 8;
  uint32_t word = 0u;
  #pragma unroll 4
  for (int q = 0; q < QQ; q++){
    float4 xv = __ldg(xp + q);
    unsigned ib = i0 + (unsigned)(q * 4);
    word |= (xv.x > tf_u01(ka, kb, ib + 0u)) ? (1u << (q * 4 + 0)) : 0u;
    word |= (xv.y > tf_u01(ka, kb, ib + 1u)) ? (1u << (q * 4 + 1)) : 0u;
    word |= (xv.z > tf_u01(ka, kb, ib + 2u)) ? (1u << (q * 4 + 2)) : 0u;
    word |= (xv.w > tf_u01(ka, kb, ib + 3u)) ? (1u << (q * 4 + 3)) : 0u;
  }
  return word;
}

// ---------------- persistent SNN kernel: 384 threads, reg headroom ----------------
__global__ __launch_bounds__(384, 1) void snn(const float* __restrict__ x,
                                              const float* __restrict__ W2,
                                              const float* __restrict__ b1,
                                              const float* __restrict__ b2,
                                              float* __restrict__ out, KeyArr keys){
  extern __shared__ uint8_t SM[];
  float* Ftab = (float*)(SM + OFF_F);
  float* Sh2m = (float*)(SM + OFF_H2M);
  float* Sh2s = (float*)(SM + OFF_H2S);
  float* Sb2  = (float*)(SM + OFF_B2);
  uint32_t SB = s2u(SM);
  uint32_t mFull = SB + OFF_MB, mEmpty = SB + OFF_MB + 32;
  int tid = threadIdx.x, lane = tid & 31, wid = tid >> 5, cta = blockIdx.x;
  int g = lane >> 2, tig = lane & 3;

  // smem tables (all threads)
  for (int i = tid; i < HID * 12; i += 384){
    int n = i / 12, o = i % 12;
    Ftab[i] = (o < 10) ? W2[o * HID + n] : (o == 10 ? b1[n] : 0.0f);
  }
  for (int i = tid; i < 1280; i += 384){ Sh2m[i] = 0.0f; Sh2s[i] = 0.0f; }
  if (tid < 10) Sb2[tid] = b2[tid];
  if (tid == 0){
    #pragma unroll
    for (int s = 0; s < 4; s++){ mbar_init(mFull + s * 8, 1); mbar_init(mEmpty + s * 8, 8); }
  }
  __syncthreads();                        // tables + mbarriers visible

  if (wid == 11){
    // ================= filler warp: weight ring service =================
    if (lane == 0){
      for (int f = 0; f < NSEQ; f++){
        int s = f & 3;
        if (f >= 4) mbar_wait(mEmpty + s * 8, (uint32_t)(((f >> 2) - 1) & 1));
        mbar_expect(mFull + s * 8, BNB);
        bulkcp(SB + OFF_B + (unsigned)s * BNB, g_wq + (unsigned)(f % NB) * BNB, mFull + s * 8);
      }
    }
  } else if (wid >= 8){
    // ================= producers (3 warps): spike masks =================
    int ptid = tid - 256;                  // 0..95
    {
      unsigned ka = keys.a[0], kb = keys.b[0];
      uint32_t* AMd = (uint32_t*)(SM + OFF_AM);
      for (int j = 0; j < 34; j++){
        int w = ptid + j * 96;
        if (w < 3200) AMd[w] = gen_word(x, ka, kb, cta, w);
      }
    }
    bar11();                               // AM(t=0) ready
    for (int t = 0; t < T_STEPS; t++){
      if (t + 1 < T_STEPS){
        unsigned ka = keys.a[t + 1], kb = keys.b[t + 1];
        uint32_t* AMd = (uint32_t*)(SM + OFF_AM + (unsigned)((t + 1) & 1) * 12800u);
        for (int j = 0; j < 34; j++){
          int w = ptid + j * 96;
          if (w < 3200) AMd[w] = gen_word(x, ka, kb, cta, w);
        }
      }
      bar11();
    }
  } else {
    // ================= consumers (8 warps) =================
    int rA = wid * 16 + g, rB = rA + 8;
    int mA = cta * 128 + rA, mB = mA + 8;
    int gbase = g * 100 + tig;
    bar11();                               // wait AM(t=0)

    for (int t = 0; t < T_STEPS; t++){
      const uint32_t* AMt = (const uint32_t*)(SM + OFF_AM + (unsigned)(t & 1) * 12800u);
      float acc10[2][10] = {};

      for (int nb = 0; nb < NB; nb++){
        int seq = t * NB + nb;
        int s = seq & 3;
        mbar_wait(mFull + s * 8, (uint32_t)((seq >> 2) & 1));   // weights(seq) in slot s

        const uint8_t* Bb = SM + OFF_B + (unsigned)s * BNB;
        int accd[6][4] = {};

        #pragma unroll
        for (int kc = 0; kc < KC; kc++){
          uint32_t mAv = AMt[rA * 25 + kc], mBv = AMt[rB * 25 + kc];
          uint32_t sa = mAv >> (tig * 4), sb = mBv >> (tig * 4);
          uint32_t a0 = ((sa & 0xFu) * 0x204081u) & 0x01010101u;
          uint32_t a2 = (((sa >> 16) & 0xFu) * 0x204081u) & 0x01010101u;
          uint32_t a1 = ((sb & 0xFu) * 0x204081u) & 0x01010101u;
          uint32_t a3 = (((sb >> 16) & 0xFu) * 0x204081u) & 0x01010101u;
          #pragma unroll
          for (int n8 = 0; n8 < 2; n8++){
            unsigned grp = (unsigned)(n8 * 800 + kc * 4 + gbase);
            uint4 v01 = *(const uint4*)(Bb + grp * 16u);
            uint2 v2  = *(const uint2*)(Bb + B01SZ + grp * 8u);
            imma(accd[n8],     a0, a1, a2, a3, v01.x, v01.y);   // d0
            imma(accd[2 + n8], a0, a1, a2, a3, v01.z, v01.w);   // d1
            imma(accd[4 + n8], a0, a1, a2, a3, v2.x,  v2.y);    // d2
          }
        }
        __syncwarp();
        if (lane == 0) mbar_arrive(mEmpty + s * 8);   // done reading slot s

        // epilogue: combine digits -> LIF1 -> GEMM2 partial
        #pragma unroll
        for (int n8 = 0; n8 < 2; n8++){
          #pragma unroll
          for (int j = 0; j < 2; j++){
            int n = nb * 16 + n8 * 8 + 2 * tig + j;
            const float4* Fp = (const float4*)(Ftab + n * 12);
            float4 F0 = Fp[0], F1 = Fp[1], F2 = Fp[2];   // w0..w9, b1 = F2.z
            #pragma unroll
            for (int r = 0; r < 2; r++){
              int ri = r * 2 + j;
              float f = fmaf(__int2float_rn(accd[4 + n8][ri]), 0.00390625f,
                        fmaf(__int2float_rn(accd[2 + n8][ri]), 1.52587890625e-05f,
                             __int2float_rn(accd[n8][ri]) * 5.9604644775390625e-08f));
              int m = r ? mB : mA;
              float* cp_ = g_c1 + (size_t)n * B_SZ + m;
              float carry = t ? *cp_ : 0.0f;
              float mem = (carry + f) + F2.z;
              bool sgn = mem > 0.5f;
              *cp_ = sgn ? 0.0f : 0.2f * mem;
              if (sgn){
                acc10[r][0] += F0.x; acc10[r][1] += F0.y; acc10[r][2] += F0.z; acc10[r][3] += F0.w;
                acc10[r][4] += F1.x; acc10[r][5] += F1.y; acc10[r][6] += F1.z; acc10[r][7] += F1.w;
                acc10[r][8] += F2.x; acc10[r][9] += F2.y;
              }
            }
          }
        }
      }

      // LIF2 + spike-sum update (per row; reduce over 4 tig lanes)
      #pragma unroll
      for (int r = 0; r < 2; r++){
        int rl = r ? rB : rA;
        #pragma unroll
        for (int o = 0; o < 10; o++){
          float v = acc10[r][o];
          v += __shfl_xor_sync(0xffffffffu, v, 1);
          v += __shfl_xor_sync(0xffffffffu, v, 2);
          if (tig == 0){
            float m2 = (Sh2m[rl * 10 + o] + v) + Sb2[o];
            bool s2 = m2 > 0.5f;
            Sh2m[rl * 10 + o] = s2 ? 0.0f : 0.2f * m2;
            Sh2s[rl * 10 + o] += s2 ? 1.0f : 0.0f;
          }
        }
      }
      bar11();
    }
  }
  __syncthreads();

  // output
  for (int i = tid; i < 1280; i += 384){
    int m = i / 10, o = i % 10;
    out[(cta * 128 + m) * 10 + o] = Sh2s[m * 10 + o] * 0.05f;
  }
}

// ---------------- launch ----------------
extern "C" void kernel_launch(void* const* d_in, const int* in_sizes, int n_in,
                              void* d_out, int out_size){
  const float* x  = (const float*)d_in[0];
  const float* W1 = (const float*)d_in[1];
  const float* b1 = (const float*)d_in[2];
  const float* W2 = (const float*)d_in[3];
  const float* b2 = (const float*)d_in[4];
  float* out = (float*)d_out;

  KeyArr keys;
  for (int t = 0; t < T_STEPS; t++){
    unsigned o0, o1;
    tf2x32(0u, 42u, 0u, (unsigned)t, o0, o1);
    keys.a[t] = o0; keys.b[t] = o1;
  }

  cudaFuncSetAttribute(snn, cudaFuncAttributeMaxDynamicSharedMemorySize, SMEM_REQ);
  prep<<<(HID * 800 + 255) / 256, 256>>>(W1);
  snn<<<128, 384, SMEM_REQ>>>(x, W2, b1, b2, out, keys);
}

// round 13
// speedup vs baseline: 1.1889x; 1.0651x over previous
#include <cuda_runtime.h>
#include <cstdint>

#define B_SZ 16384
#define IN_DIM 784
#define HID 400
#define T_STEPS 20
#define NB 25
#define KC 25
#define NSEQ (T_STEPS*NB)
#define BNB 38400u
#define B01SZ 25600u
#define OFF_B   0u        // 4 x 38400 ring
#define OFF_AM  153600u   // 2 x 12800 mask double buffer
#define OFF_F   179200u   // 400 x 12 floats
#define OFF_H2M 198400u
#define OFF_H2S 203520u
#define OFF_B2  208640u
#define OFF_MB  208704u
#define SMEM_REQ 208832

__device__ __align__(128) uint8_t g_wq[NB * BNB];
__device__ float g_c1[HID * B_SZ];                 // LIF1 carry [n][m]

struct KeyArr { unsigned a[T_STEPS], b[T_STEPS]; };

__host__ __device__ __forceinline__ void tfr(unsigned &x0, unsigned &x1, int r){
  x0 += x1;
#ifdef __CUDA_ARCH__
  x1 = __funnelshift_l(x1, x1, r);
#else
  x1 = (x1 << r) | (x1 >> (32 - r));
#endif
  x1 ^= x0;
}
__host__ __device__ __forceinline__ void tf2x32(unsigned k0, unsigned k1,
                                                unsigned x0, unsigned x1,
                                                unsigned &o0, unsigned &o1){
  unsigned k2 = k0 ^ k1 ^ 0x1BD11BDAu;
  x0 += k0; x1 += k1;
  tfr(x0,x1,13); tfr(x0,x1,15); tfr(x0,x1,26); tfr(x0,x1,6);  x0 += k1; x1 += k2 + 1u;
  tfr(x0,x1,17); tfr(x0,x1,29); tfr(x0,x1,16); tfr(x0,x1,24); x0 += k2; x1 += k0 + 2u;
  tfr(x0,x1,13); tfr(x0,x1,15); tfr(x0,x1,26); tfr(x0,x1,6);  x0 += k0; x1 += k1 + 3u;
  tfr(x0,x1,17); tfr(x0,x1,29); tfr(x0,x1,16); tfr(x0,x1,24); x0 += k1; x1 += k2 + 4u;
  tfr(x0,x1,13); tfr(x0,x1,15); tfr(x0,x1,26); tfr(x0,x1,6);  x0 += k2; x1 += k0 + 5u;
  o0 = x0; o1 = x1;
}
__device__ __forceinline__ float tf_u01(unsigned ka, unsigned kb, unsigned i){
  unsigned o0, o1; tf2x32(ka, kb, 0u, i, o0, o1);
  return __uint_as_float((((o0 ^ o1) >> 9) | 0x3f800000u)) - 1.0f;
}

__global__ __launch_bounds__(256) void prep(const float* __restrict__ W1){
  int i = blockIdx.x * 256 + threadIdx.x;
  if (i >= HID * 800) return;
  int n = i / 800, k = i % 800;
  float w = (k < IN_DIM) ? W1[n * IN_DIM + k] : 0.0f;
  int v = __float2int_rn(w * 16777216.0f);          // w * 2^24
  int d0 = ((v & 0xFF) ^ 0x80) - 0x80;  v = (v - d0) >> 8;
  int d1 = ((v & 0xFF) ^ 0x80) - 0x80;  v = (v - d1) >> 8;
  int d2 = v;
  int nb = n / 16, nn = n % 16;
  int kc = k >> 5, kk = k & 31;
  int half = kk >> 4, tig = (kk & 15) >> 2, j = kk & 3;
  unsigned grp = (unsigned)(nn * KC + kc) * 4u + (unsigned)tig;
  uint8_t* base = g_wq + (unsigned)nb * BNB;
  base[grp * 16u + 0u + half * 4u + j]   = (uint8_t)d0;
  base[grp * 16u + 8u + half * 4u + j]   = (uint8_t)d1;
  base[B01SZ + grp * 8u + half * 4u + j] = (uint8_t)d2;
}

__device__ __forceinline__ uint32_t s2u(const void* p){
  uint32_t a; asm("{ .reg .u64 t; cvta.to.shared.u64 t, %1; cvt.u32.u64 %0, t; }" : "=r"(a) : "l"(p));
  return a;
}
__device__ __forceinline__ void imma(int* c, uint32_t a0, uint32_t a1, uint32_t a2,
                                     uint32_t a3, uint32_t b0, uint32_t b1){
  asm volatile("mma.sync.aligned.m16n8k32.row.col.s32.s8.s8.s32 "
               "{%0,%1,%2,%3}, {%4,%5,%6,%7}, {%8,%9}, {%0,%1,%2,%3};"
               : "+r"(c[0]), "+r"(c[1]), "+r"(c[2]), "+r"(c[3])
               : "r"(a0), "r"(a1), "r"(a2), "r"(a3), "r"(b0), "r"(b1));
}
__device__ __forceinline__ void mbar_init(uint32_t mb, uint32_t n){
  asm volatile("mbarrier.init.shared.b64 [%0], %1;" :: "r"(mb), "r"(n) : "memory");
}
__device__ __forceinline__ void mbar_expect(uint32_t mb, uint32_t bytes){
  asm volatile("mbarrier.arrive.expect_tx.shared.b64 _, [%0], %1;" :: "r"(mb), "r"(bytes) : "memory");
}
__device__ __forceinline__ void mbar_arrive(uint32_t mb){
  asm volatile("mbarrier.arrive.shared.b64 _, [%0];" :: "r"(mb) : "memory");
}
__device__ __forceinline__ void mbar_wait(uint32_t mb, uint32_t ph){
  asm volatile("{ .reg .pred P; W_%=:\n\t"
    "mbarrier.try_wait.parity.acquire.cta.shared::cta.b64 P, [%0], %1, 0x989680;\n\t"
    "@!P bra W_%=; }" :: "r"(mb), "r"(ph) : "memory");
}
__device__ __forceinline__ void bulkcp(uint32_t dst, const void* src, uint32_t mb){
  asm volatile("cp.async.bulk.shared::cluster.global.mbarrier::complete_tx::bytes [%0], [%1], %2, [%3];"
    :: "r"(dst), "l"(src), "r"(BNB), "r"(mb) : "memory");
}
__device__ __forceinline__ void bar11(){
  asm volatile("bar.sync 1, 352;" ::: "memory");
}
__device__ __forceinline__ uint32_t gen_word(const float* __restrict__ x,
                                             unsigned ka, unsigned kb, int cta, int w){
  int row = w / 25, wi = w - row * 25;
  unsigned i0 = (unsigned)(cta * 128 + row) * IN_DIM + (unsigned)(wi * 32);
  const float4* xp = (const float4*)(x + i0);
  int QQ = (wi == 24) ? 4 : 8;
  uint32_t word = 0u;
  #pragma unroll 4
  for (int q = 0; q < QQ; q++){
    float4 xv = __ldg(xp + q);
    unsigned ib = i0 + (unsigned)(q * 4);
    word |= (xv.x > tf_u01(ka, kb, ib + 0u)) ? (1u << (q * 4 + 0)) : 0u;
    word |= (xv.y > tf_u01(ka, kb, ib + 1u)) ? (1u << (q * 4 + 1)) : 0u;
    word |= (xv.z > tf_u01(ka, kb, ib + 2u)) ? (1u << (q * 4 + 2)) : 0u;
    word |= (xv.w > tf_u01(ka, kb, ib + 3u)) ? (1u << (q * 4 + 3)) : 0u;
  }
  return word;
}

// deferred epilogue for block nbP (bit-exact vs original ordering)
#define EPI do{ \
  _Pragma("unroll") \
  for (int q = 0; q < 8; q++){ \
    int n8_ = q >> 2, j_ = (q >> 1) & 1, r_ = q & 1; \
    int n_ = nbP * 16 + n8_ * 8 + 2 * tig + j_; \
    const float4* Fp_ = (const float4*)(Ftab + n_ * 12); \
    float4 F0_ = Fp_[0], F1_ = Fp_[1], F2_ = Fp_[2]; \
    int ri_ = r_ * 2 + j_; \
    float f_ = fmaf(__int2float_rn(accdP[4 + n8_][ri_]), 0.00390625f, \
               fmaf(__int2float_rn(accdP[2 + n8_][ri_]), 1.52587890625e-05f, \
                    __int2float_rn(accdP[n8_][ri_]) * 5.9604644775390625e-08f)); \
    float mem_ = (crP[q] + f_) + F2_.z; \
    bool sgn_ = mem_ > 0.5f; \
    g_c1[(size_t)n_ * B_SZ + (r_ ? mB : mA)] = sgn_ ? 0.0f : 0.2f * mem_; \
    if (sgn_){ \
      acc10[r_][0] += F0_.x; acc10[r_][1] += F0_.y; acc10[r_][2] += F0_.z; acc10[r_][3] += F0_.w; \
      acc10[r_][4] += F1_.x; acc10[r_][5] += F1_.y; acc10[r_][6] += F1_.z; acc10[r_][7] += F1_.w; \
      acc10[r_][8] += F2_.x; acc10[r_][9] += F2_.y; \
    } \
  } \
}while(0)

#define KCBODY(kc) { \
  uint32_t mAv = AMt[rA * 25 + (kc)], mBv = AMt[rB * 25 + (kc)]; \
  uint32_t sa_ = mAv >> (tig * 4), sb_ = mBv >> (tig * 4); \
  uint32_t a0 = ((sa_ & 0xFu) * 0x204081u) & 0x01010101u; \
  uint32_t a2 = (((sa_ >> 16) & 0xFu) * 0x204081u) & 0x01010101u; \
  uint32_t a1 = ((sb_ & 0xFu) * 0x204081u) & 0x01010101u; \
  uint32_t a3 = (((sb_ >> 16) & 0xFu) * 0x204081u) & 0x01010101u; \
  _Pragma("unroll") \
  for (int n8 = 0; n8 < 2; n8++){ \
    unsigned grp = (unsigned)(n8 * 800 + (kc) * 4 + gbase); \
    uint4 v01 = *(const uint4*)(Bb + grp * 16u); \
    uint2 v2  = *(const uint2*)(Bb + B01SZ + grp * 8u); \
    imma(accd[n8],     a0, a1, a2, a3, v01.x, v01.y); \
    imma(accd[2 + n8], a0, a1, a2, a3, v01.z, v01.w); \
    imma(accd[4 + n8], a0, a1, a2, a3, v2.x,  v2.y); \
  } \
}

__global__ __launch_bounds__(384, 1) void snn(const float* __restrict__ x,
                                              const float* __restrict__ W2,
                                              const float* __restrict__ b1,
                                              const float* __restrict__ b2,
                                              float* __restrict__ out, KeyArr keys){
  extern __shared__ uint8_t SM[];
  float* Ftab = (float*)(SM + OFF_F);
  float* Sh2m = (float*)(SM + OFF_H2M);
  float* Sh2s = (float*)(SM + OFF_H2S);
  float* Sb2  = (float*)(SM + OFF_B2);
  uint32_t SB = s2u(SM);
  uint32_t mFull = SB + OFF_MB, mEmpty = SB + OFF_MB + 32;
  int tid = threadIdx.x, lane = tid & 31, wid = tid >> 5, cta = blockIdx.x;
  int g = lane >> 2, tig = lane & 3;

  for (int i = tid; i < HID * 12; i += 384){
    int n = i / 12, o = i % 12;
    Ftab[i] = (o < 10) ? W2[o * HID + n] : (o == 10 ? b1[n] : 0.0f);
  }
  for (int i = tid; i < 1280; i += 384){ Sh2m[i] = 0.0f; Sh2s[i] = 0.0f; }
  if (tid < 10) Sb2[tid] = b2[tid];
  if (tid == 0){
    #pragma unroll
    for (int s = 0; s < 4; s++){ mbar_init(mFull + s * 8, 1); mbar_init(mEmpty + s * 8, 8); }
  }
  __syncthreads();

  if (wid == 11){
    if (lane == 0){
      for (int f = 0; f < NSEQ; f++){
        int s = f & 3;
        if (f >= 4) mbar_wait(mEmpty + s * 8, (uint32_t)(((f >> 2) - 1) & 1));
        mbar_expect(mFull + s * 8, BNB);
        bulkcp(SB + OFF_B + (unsigned)s * BNB, g_wq + (unsigned)(f % NB) * BNB, mFull + s * 8);
      }
    }
  } else if (wid >= 8){
    int ptid = tid - 256;
    {
      unsigned ka = keys.a[0], kb = keys.b[0];
      uint32_t* AMd = (uint32_t*)(SM + OFF_AM);
      for (int j = 0; j < 34; j++){
        int w = ptid + j * 96;
        if (w < 3200) AMd[w] = gen_word(x, ka, kb, cta, w);
      }
    }
    bar11();
    for (int t = 0; t < T_STEPS; t++){
      if (t + 1 < T_STEPS){
        unsigned ka = keys.a[t + 1], kb = keys.b[t + 1];
        uint32_t* AMd = (uint32_t*)(SM + OFF_AM + (unsigned)((t + 1) & 1) * 12800u);
        for (int j = 0; j < 34; j++){
          int w = ptid + j * 96;
          if (w < 3200) AMd[w] = gen_word(x, ka, kb, cta, w);
        }
      }
      bar11();
    }
  } else {
    // ================= consumers (8 warps) =================
    int rA = wid * 16 + g, rB = rA + 8;
    int mA = cta * 128 + rA, mB = mA + 8;
    int gbase = g * 100 + tig;
    bar11();

    for (int t = 0; t < T_STEPS; t++){
      const uint32_t* AMt = (const uint32_t*)(SM + OFF_AM + (unsigned)(t & 1) * 12800u);
      float acc10[2][10] = {};
      int accdP[6][4]; float crP[8]; int nbP = -1;

      for (int nb = 0; nb < NB; nb++){
        int seq = t * NB + nb;
        int s = seq & 3;
        mbar_wait(mFull + s * 8, (uint32_t)((seq >> 2) & 1));

        // prefetch this block's carries (consumed one block later)
        float cr[8];
        #pragma unroll
        for (int q = 0; q < 8; q++){
          int n8_ = q >> 2, j_ = (q >> 1) & 1, r_ = q & 1;
          int n_ = nb * 16 + n8_ * 8 + 2 * tig + j_;
          cr[q] = t ? g_c1[(size_t)n_ * B_SZ + (r_ ? mB : mA)] : 0.0f;
        }

        const uint8_t* Bb = SM + OFF_B + (unsigned)s * BNB;
        int accd[6][4] = {};

        if ((wid & 1) == 0 && nbP >= 0) EPI;      // even warps: epilogue(prev) up front
        #pragma unroll
        for (int kc = 0; kc < 12; kc++) KCBODY(kc)
        if ((wid & 1) == 1 && nbP >= 0) EPI;      // odd warps: epilogue(prev) mid-loop
        #pragma unroll
        for (int kc = 12; kc < KC; kc++) KCBODY(kc)

        __syncwarp();
        if (lane == 0) mbar_arrive(mEmpty + s * 8);

        #pragma unroll
        for (int i = 0; i < 6; i++)
          #pragma unroll
          for (int jj = 0; jj < 4; jj++) accdP[i][jj] = accd[i][jj];
        #pragma unroll
        for (int q = 0; q < 8; q++) crP[q] = cr[q];
        nbP = nb;
      }
      EPI;                                        // final block's epilogue (nbP == 24)

      // LIF2 + spike-sum (unchanged ordering)
      #pragma unroll
      for (int r = 0; r < 2; r++){
        int rl = r ? rB : rA;
        #pragma unroll
        for (int o = 0; o < 10; o++){
          float v = acc10[r][o];
          v += __shfl_xor_sync(0xffffffffu, v, 1);
          v += __shfl_xor_sync(0xffffffffu, v, 2);
          if (tig == 0){
            float m2 = (Sh2m[rl * 10 + o] + v) + Sb2[o];
            bool s2 = m2 > 0.5f;
            Sh2m[rl * 10 + o] = s2 ? 0.0f : 0.2f * m2;
            Sh2s[rl * 10 + o] += s2 ? 1.0f : 0.0f;
          }
        }
      }
      bar11();
    }
  }
  __syncthreads();

  for (int i = tid; i < 1280; i += 384){
    int m = i / 10, o = i % 10;
    out[(cta * 128 + m) * 10 + o] = Sh2s[m * 10 + o] * 0.05f;
  }
}

extern "C" void kernel_launch(void* const* d_in, const int* in_sizes, int n_in,
                              void* d_out, int out_size){
  const float* x  = (const float*)d_in[0];
  const float* W1 = (const float*)d_in[1];
  const float* b1 = (const float*)d_in[2];
  const float* W2 = (const float*)d_in[3];
  const float* b2 = (const float*)d_in[4];
  float* out = (float*)d_out;

  KeyArr keys;
  for (int t = 0; t < T_STEPS; t++){
    unsigned o0, o1;
    tf2x32(0u, 42u, 0u, (unsigned)t, o0, o1);
    keys.a[t] = o0; keys.b[t] = o1;
  }

  cudaFuncSetAttribute(snn, cudaFuncAttributeMaxDynamicSharedMemorySize, SMEM_REQ);
  prep<<<(HID * 800 + 255) / 256, 256>>>(W1);
  snn<<<128, 384, SMEM_REQ>>>(x, W2, b1, b2, out, keys);
}